// round 14
// baseline (speedup 1.0000x reference)
#include <cuda_runtime.h>
#include <math.h>
#include <float.h>

#define KF 32768
#define KI 16384
#define BB 16
#define HH 32
#define NROW (BB*HH)
#define NSEG 16                // score segments per row
#define HPB 8                  // heads per score block
#define GAMMA_C 0.3f
#define EPS_C 1e-6f
#define L2E 1.4426950408889634f

// ---- scratch (static device arrays; no allocations) ----
__device__ float g_RI[BB * KF * 2];        // interleaved (rf, indicator) per position
__device__ float g_part[NROW * NSEG * 4];  // per (row,seg): zi, p, sm, pad
__device__ float g_ca[NROW];               // GAMMA * m_pos
__device__ float g_cb[NROW];               // GAMMA * m_neg

__device__ __forceinline__ float fast_ex2(float x) {
    float y;
    asm("ex2.approx.ftz.f32 %0, %1;" : "=f"(y) : "f"(x));
    return y;
}

struct F8 { float v[8]; };

// 256-bit global load with L2 evict_last (legal form: .v8.b32)
__device__ __forceinline__ F8 ldg256_evict_last(const float* p) {
    unsigned r0, r1, r2, r3, r4, r5, r6, r7;
    asm volatile("ld.global.L2::evict_last.v8.b32 {%0,%1,%2,%3,%4,%5,%6,%7}, [%8];"
                 : "=r"(r0), "=r"(r1), "=r"(r2), "=r"(r3),
                   "=r"(r4), "=r"(r5), "=r"(r6), "=r"(r7)
                 : "l"(p));
    F8 o;
    o.v[0] = __uint_as_float(r0); o.v[1] = __uint_as_float(r1);
    o.v[2] = __uint_as_float(r2); o.v[3] = __uint_as_float(r3);
    o.v[4] = __uint_as_float(r4); o.v[5] = __uint_as_float(r5);
    o.v[6] = __uint_as_float(r6); o.v[7] = __uint_as_float(r7);
    return o;
}

// ============================================================
// Kernel 1: per-batch stats + mask scan + rf + pack (R,I). grid=16, block=1024
// ============================================================
__global__ void __launch_bounds__(1024) pack_kernel(
    const float* __restrict__ fC, const float* __restrict__ fA,
    const float* __restrict__ fD, const float* __restrict__ fB,
    const int* __restrict__ mask)
{
    const int b = blockIdx.x;
    const int tid = threadIdx.x;
    const int lane = tid & 31, warp = tid >> 5;
    const float* ptr[4] = {fC + b*KI, fA + b*KI, fD + b*KI, fB + b*KI};

    // --- stats: sum & sumsq for 4 features ---
    float acc[8];
#pragma unroll
    for (int i = 0; i < 8; i++) acc[i] = 0.f;
    for (int j = tid; j < KI/4; j += 1024) {
#pragma unroll
        for (int f = 0; f < 4; f++) {
            float4 v = ((const float4*)ptr[f])[j];
            acc[2*f]   += (v.x + v.y) + (v.z + v.w);
            acc[2*f+1] += (v.x*v.x + v.y*v.y) + (v.z*v.z + v.w*v.w);
        }
    }
#pragma unroll
    for (int off = 16; off; off >>= 1)
#pragma unroll
        for (int i = 0; i < 8; i++)
            acc[i] += __shfl_down_sync(0xffffffffu, acc[i], off);

    __shared__ float red[8][32];
    if (lane == 0)
#pragma unroll
        for (int i = 0; i < 8; i++) red[i][warp] = acc[i];
    __syncthreads();

    __shared__ float s_mu[4], s_inv[4];
    if (tid < 32) {
#pragma unroll
        for (int i = 0; i < 8; i++) acc[i] = red[i][tid];
#pragma unroll
        for (int off = 16; off; off >>= 1)
#pragma unroll
            for (int i = 0; i < 8; i++)
                acc[i] += __shfl_down_sync(0xffffffffu, acc[i], off);
        if (tid == 0) {
#pragma unroll
            for (int f = 0; f < 4; f++) {
                float mu = acc[2*f] * (1.f / KI);
                float var = acc[2*f+1] * (1.f / KI) - mu * mu;
                float sd = sqrtf(fmaxf(var, 0.f));
                s_mu[f] = mu;
                s_inv[f] = 1.f / (sd + EPS_C);
            }
        }
    }
    __syncthreads();

    // --- mask scan ---
    const int base = b * KF + tid * 32;
    int mbits[32];
    int cnt = 0;
#pragma unroll
    for (int i = 0; i < 32; i += 4) {
        int4 mm = *(const int4*)(mask + base + i);
        mbits[i] = mm.x; mbits[i+1] = mm.y; mbits[i+2] = mm.z; mbits[i+3] = mm.w;
        cnt += mm.x + mm.y + mm.z + mm.w;
    }
    int inc = cnt;
#pragma unroll
    for (int off = 1; off < 32; off <<= 1) {
        int v = __shfl_up_sync(0xffffffffu, inc, off);
        if (lane >= off) inc += v;
    }
    __shared__ int wsum[32];
    if (lane == 31) wsum[warp] = inc;
    __syncthreads();
    if (tid < 32) {
        int v = wsum[tid];
        int ssum = v;
#pragma unroll
        for (int off = 1; off < 32; off <<= 1) {
            int u = __shfl_up_sync(0xffffffffu, ssum, off);
            if (tid >= off) ssum += u;
        }
        wsum[tid] = ssum - v;
    }
    __syncthreads();
    int r = wsum[warp] + inc - cnt;   // rank of first image position in this thread's chunk

    const float mu0 = s_mu[0], iv0 = s_inv[0];
    const float mu1 = s_mu[1], iv1 = s_inv[1];
    const float mu2 = s_mu[2], iv2 = s_inv[2];
    const float mu3 = s_mu[3], iv3 = s_inv[3];

    float4* RIp = (float4*)(g_RI + (size_t)base * 2);   // 2 floats per position
#pragma unroll
    for (int c = 0; c < 8; c++) {
        float rv[4], iv[4];
#pragma unroll
        for (int e = 0; e < 4; e++) {
            if (mbits[c*4 + e]) {
                float zc = (ptr[0][r] - mu0) * iv0;
                float za = (ptr[1][r] - mu1) * iv1;
                float zd = (ptr[2][r] - mu2) * iv2;
                float zb = (ptr[3][r] - mu3) * iv3;
                float Ct = fmaxf(zc, 0.f);
                float At = 1.f / (1.f + fast_ex2(-za * L2E));
                float Dt = 1.f / (1.f + fast_ex2(-zd * L2E));
                float Bt = 1.f / (1.f + fast_ex2(-zb * L2E));
                float denom = fmaxf(1.f + 0.5f * (Dt + Bt), EPS_C);
                rv[e] = Ct * At / denom;
                iv[e] = 1.f;
                r++;
            } else {
                rv[e] = 0.f; iv[e] = 0.f;
            }
        }
        RIp[c*2]     = make_float4(rv[0], iv[0], rv[1], iv[1]);
        RIp[c*2 + 1] = make_float4(rv[2], iv[2], rv[3], iv[3]);
    }
}

// ============================================================
// Kernel 2: score — 8 heads per block, (R,I) stream loaded once, LDG.256.
// grid = BB * (HH/HPB) * NSEG = 1024, block = 256.
// Each thread: one float8 per head. Per head: zi=Σe·I, p=Σe·R, sm=Σe·min(R,1).
// ============================================================
__global__ void __launch_bounds__(256) score_kernel(const float* __restrict__ attn)
{
    const int bx  = blockIdx.x;
    const int b   = bx >> 6;             // / 64
    const int hg  = (bx >> 4) & 3;
    const int seg = bx & 15;
    const int tid = threadIdx.x;

    const int row0 = b * HH + hg * HPB;
    const int i8 = seg * 256 + tid;                 // float8 index within row (4096/row)
    const float* A0 = attn + (size_t)row0 * KF + (size_t)i8 * 8;
    const float4* RIf4 = (const float4*)(g_RI + (size_t)b * KF * 2) + (size_t)i8 * 4;

    // weight vectors for this thread's 8 positions
    float R[8], I[8], M[8];
#pragma unroll
    for (int c = 0; c < 4; c++) {
        float4 ri = RIf4[c];
        R[2*c]   = ri.x; I[2*c]   = ri.y;
        R[2*c+1] = ri.z; I[2*c+1] = ri.w;
        M[2*c]   = fminf(ri.x, 1.f);
        M[2*c+1] = fminf(ri.z, 1.f);
    }

    float zi[HPB], p[HPB], sm[HPB];
#pragma unroll
    for (int h = 0; h < HPB; h++) { zi[h] = 0.f; p[h] = 0.f; sm[h] = 0.f; }

#pragma unroll
    for (int h = 0; h < HPB; h++) {
        F8 x = ldg256_evict_last(A0 + (size_t)h * KF);
#pragma unroll
        for (int e = 0; e < 8; e++) {
            float ev = fast_ex2(x.v[e] * L2E);
            zi[h] = fmaf(ev, I[e], zi[h]);
            p[h]  = fmaf(ev, R[e], p[h]);
            sm[h] = fmaf(ev, M[e], sm[h]);
        }
    }

    // intra-warp reduce all 24 accumulators
#pragma unroll
    for (int off = 16; off; off >>= 1) {
#pragma unroll
        for (int h = 0; h < HPB; h++) {
            zi[h] += __shfl_down_sync(0xffffffffu, zi[h], off);
            p[h]  += __shfl_down_sync(0xffffffffu, p[h],  off);
            sm[h] += __shfl_down_sync(0xffffffffu, sm[h], off);
        }
    }
    __shared__ float sred[8][HPB][3];
    const int lane = tid & 31, warp = tid >> 5;
    if (lane == 0) {
#pragma unroll
        for (int h = 0; h < HPB; h++) {
            sred[warp][h][0] = zi[h];
            sred[warp][h][1] = p[h];
            sred[warp][h][2] = sm[h];
        }
    }
    __syncthreads();
    if (tid < HPB) {
        float a0 = 0.f, a1 = 0.f, a2 = 0.f;
#pragma unroll
        for (int w = 0; w < 8; w++) {
            a0 += sred[w][tid][0];
            a1 += sred[w][tid][1];
            a2 += sred[w][tid][2];
        }
        float4* dst = (float4*)(g_part + (size_t)((row0 + tid) * NSEG + seg) * 4);
        *dst = make_float4(a0, a1, a2, 0.f);
    }
}

// ============================================================
// Kernel 3: finalize + warp-argmax top-7 per batch. grid=1, block=512
// ============================================================
__global__ void __launch_bounds__(512) select_kernel()
{
    const int tid = threadIdx.x;       // tid == row == b*32 + h
    const int lane = tid & 31;

    // finalize: fixed-order combine of NSEG partials
    const float4* pp = (const float4*)(g_part + (size_t)tid * NSEG * 4);
    float zi = 0.f, p = 0.f, sm = 0.f;
#pragma unroll
    for (int k = 0; k < NSEG; k++) {
        float4 v = pp[k];
        zi += v.x; p += v.y; sm += v.z;
    }
    const float sp = p / zi;
    const float sn = (zi - sm) / zi;

    // top-7 on sp within warp (lane = head); strict >, lowest index wins ties
    bool sel = false;
#pragma unroll
    for (int t = 0; t < 7; t++) {
        float cv = sel ? -FLT_MAX : sp;
        int ci = lane;
#pragma unroll
        for (int off = 16; off; off >>= 1) {
            float ov = __shfl_down_sync(0xffffffffu, cv, off);
            int   oi = __shfl_down_sync(0xffffffffu, ci, off);
            if (ov > cv || (ov == cv && oi < ci)) { cv = ov; ci = oi; }
        }
        int win = __shfl_sync(0xffffffffu, ci, 0);
        if (lane == win) sel = true;
    }
    const bool mpos = sel && (sp > 0.f);

    // top-7 on sn with m_pos heads masked out
    const float ns = mpos ? -FLT_MAX : sn;
    sel = false;
#pragma unroll
    for (int t = 0; t < 7; t++) {
        float cv = sel ? -FLT_MAX : ns;
        int ci = lane;
#pragma unroll
        for (int off = 16; off; off >>= 1) {
            float ov = __shfl_down_sync(0xffffffffu, cv, off);
            int   oi = __shfl_down_sync(0xffffffffu, ci, off);
            if (ov > cv || (ov == cv && oi < ci)) { cv = ov; ci = oi; }
        }
        int win = __shfl_sync(0xffffffffu, ci, 0);
        if (lane == win) sel = true;
    }
    const bool mneg = sel && (ns > 0.f);   // mpos heads have ns=-FLT_MAX, never >0

    g_ca[tid] = mpos ? GAMMA_C : 0.f;
    g_cb[tid] = mneg ? GAMMA_C : 0.f;
}

// ============================================================
// Kernel 4: out = attn + a*R - c*W,  W = max(1-R,0)*I.
// grid = NROW*16 = 8192, block=256. attn via ldcs (L2-warm), out via stcs.
// ============================================================
__global__ void __launch_bounds__(256) apply_kernel(const float* __restrict__ attn,
                                                    float* __restrict__ out)
{
    const int bh   = blockIdx.x >> 4;
    const int seg  = blockIdx.x & 15;
    const int base = bh * 8192 + seg * 512 + threadIdx.x;
    const int b    = bh >> 5;

    const float4* Ap = (const float4*)attn;
    float4* Op = (float4*)out;

    float4 x0 = __ldcs(&Ap[base]);
    float4 x1 = __ldcs(&Ap[base + 256]);
    float a = g_ca[bh];
    float c = g_cb[bh];

    if (a == 0.f && c == 0.f) {
        __stcs(&Op[base], x0);
        __stcs(&Op[base + 256], x1);
        return;
    }

    const int pidx = seg * 512 + threadIdx.x;   // float4-of-positions index
    const float4* RIf4 = (const float4*)(g_RI + (size_t)b * KF * 2);
    float4 ra = RIf4[2*pidx];
    float4 rb = RIf4[2*pidx + 1];
    float4 rc = RIf4[2*(pidx + 256)];
    float4 rd = RIf4[2*(pidx + 256) + 1];

    float4 o0, o1;
    {
        float R, I, w;
        R = ra.x; I = ra.y; w = fmaxf(1.f - R, 0.f) * I;
        o0.x = fmaf(a, R, fmaf(-c, w, x0.x));
        R = ra.z; I = ra.w; w = fmaxf(1.f - R, 0.f) * I;
        o0.y = fmaf(a, R, fmaf(-c, w, x0.y));
        R = rb.x; I = rb.y; w = fmaxf(1.f - R, 0.f) * I;
        o0.z = fmaf(a, R, fmaf(-c, w, x0.z));
        R = rb.z; I = rb.w; w = fmaxf(1.f - R, 0.f) * I;
        o0.w = fmaf(a, R, fmaf(-c, w, x0.w));
        R = rc.x; I = rc.y; w = fmaxf(1.f - R, 0.f) * I;
        o1.x = fmaf(a, R, fmaf(-c, w, x1.x));
        R = rc.z; I = rc.w; w = fmaxf(1.f - R, 0.f) * I;
        o1.y = fmaf(a, R, fmaf(-c, w, x1.y));
        R = rd.x; I = rd.y; w = fmaxf(1.f - R, 0.f) * I;
        o1.z = fmaf(a, R, fmaf(-c, w, x1.z));
        R = rd.z; I = rd.w; w = fmaxf(1.f - R, 0.f) * I;
        o1.w = fmaf(a, R, fmaf(-c, w, x1.w));
    }
    __stcs(&Op[base], o0);
    __stcs(&Op[base + 256], o1);
}

// ============================================================
extern "C" void kernel_launch(void* const* d_in, const int* in_sizes, int n_in,
                              void* d_out, int out_size)
{
    const float* attn = (const float*)d_in[0];
    const int*   mask = (const int*)  d_in[1];
    const float* fC   = (const float*)d_in[2];
    const float* fA   = (const float*)d_in[3];
    const float* fD   = (const float*)d_in[4];
    const float* fB   = (const float*)d_in[5];
    float* out = (float*)d_out;

    pack_kernel<<<BB, 1024>>>(fC, fA, fD, fB, mask);
    score_kernel<<<BB * (HH/HPB) * NSEG, 256>>>(attn);
    select_kernel<<<1, 512>>>();
    apply_kernel<<<NROW * 16, 256>>>(attn, out);
}

// round 15
// speedup vs baseline: 1.0560x; 1.0560x over previous
#include <cuda_runtime.h>
#include <math.h>
#include <float.h>

#define KF 32768
#define KI 16384
#define BB 16
#define HH 32
#define NROW (BB*HH)           // 512
#define SEGC 64                // score segments per row (64 f8 each)
#define GRID 444               // 148 SM * 3 blocks, all co-resident
#define GAMMA_C 0.3f
#define EPS_C 1e-6f
#define L2E 1.4426950408889634f

// ---- scratch (static device arrays; no allocations) ----
__device__ float  g_RI[BB * KF * 2];      // interleaved (rf, indicator)
__device__ float  g_pstat[256 * 2];       // partial (sum,sumsq) per (b,f,quarter)
__device__ int    g_ccnt[BB * 8];         // mask ones per 4096-chunk
__device__ int    g_cbase[BB * 8];        // exclusive scan of chunk counts
__device__ float  g_mu[64], g_ivs[64];    // per (b,f)
__device__ float4 g_part[NROW * SEGC];    // per (row,seg): zi,p,sm,0
__device__ float  g_ca[NROW], g_cb[NROW];
__device__ unsigned g_cnt;                // barrier arrivals
__device__ volatile unsigned g_sense;     // barrier sense (monotonic)

__device__ __forceinline__ float fast_ex2(float x) {
    float y;
    asm("ex2.approx.ftz.f32 %0, %1;" : "=f"(y) : "f"(x));
    return y;
}

struct F8 { float v[8]; };
__device__ __forceinline__ F8 ldg256_el(const float* p) {
    unsigned r0,r1,r2,r3,r4,r5,r6,r7;
    asm volatile("ld.global.L2::evict_last.v8.b32 {%0,%1,%2,%3,%4,%5,%6,%7}, [%8];"
                 : "=r"(r0),"=r"(r1),"=r"(r2),"=r"(r3),
                   "=r"(r4),"=r"(r5),"=r"(r6),"=r"(r7) : "l"(p));
    F8 o;
    o.v[0]=__uint_as_float(r0); o.v[1]=__uint_as_float(r1);
    o.v[2]=__uint_as_float(r2); o.v[3]=__uint_as_float(r3);
    o.v[4]=__uint_as_float(r4); o.v[5]=__uint_as_float(r5);
    o.v[6]=__uint_as_float(r6); o.v[7]=__uint_as_float(r7);
    return o;
}

// grid barrier: all GRID blocks co-resident (enforced by __launch_bounds__)
__device__ __forceinline__ void gsync(unsigned& ls) {
    __threadfence();            // flush this thread's writes
    __syncthreads();
    if (threadIdx.x == 0) {
        ls++;
        if (atomicAdd(&g_cnt, 1u) == GRID - 1) {
            atomicExch(&g_cnt, 0u);
            __threadfence();
            g_sense = ls;       // release
        } else {
            while (g_sense != ls) __nanosleep(64);
            __threadfence();
        }
    }
    __syncthreads();
}

__global__ void __launch_bounds__(256, 3) fused_kernel(
    const float* __restrict__ attn, const int* __restrict__ mask,
    const float* __restrict__ fC, const float* __restrict__ fA,
    const float* __restrict__ fD, const float* __restrict__ fB,
    float* __restrict__ out)
{
    const int bx = blockIdx.x;
    const int tid = threadIdx.x;
    const int lane = tid & 31, warp = tid >> 5;
    unsigned ls = g_sense;   // stable at kernel start

    __shared__ float s_r1[8], s_r2[8];
    __shared__ int   s_wsum[8];

    const float* fptr[4] = {fC, fA, fD, fB};

    // ================= Phase A: stats partials + mask chunk counts =================
    if (bx < 256) {
        const int bf = bx >> 2, quarter = bx & 3;
        const int b = bf >> 2, f = bf & 3;
        const float4* P = (const float4*)(fptr[f] + b * KI + quarter * 4096);
        float s = 0.f, s2 = 0.f;
#pragma unroll
        for (int k = 0; k < 4; k++) {
            float4 v = P[tid + k * 256];
            s  += (v.x + v.y) + (v.z + v.w);
            s2 += (v.x*v.x + v.y*v.y) + (v.z*v.z + v.w*v.w);
        }
#pragma unroll
        for (int off = 16; off; off >>= 1) {
            s  += __shfl_down_sync(0xffffffffu, s,  off);
            s2 += __shfl_down_sync(0xffffffffu, s2, off);
        }
        if (lane == 0) { s_r1[warp] = s; s_r2[warp] = s2; }
        __syncthreads();
        if (tid == 0) {
            s = 0.f; s2 = 0.f;
#pragma unroll
            for (int w = 0; w < 8; w++) { s += s_r1[w]; s2 += s_r2[w]; }
            g_pstat[bx*2]   = s;
            g_pstat[bx*2+1] = s2;
        }
    } else if (bx < 384) {
        const int cu = bx - 256;         // b*8 + chunk
        const int b = cu >> 3, chunk = cu & 7;
        const int4* M = (const int4*)(mask + b * KF + chunk * 4096);
        int cnt = 0;
#pragma unroll
        for (int k = 0; k < 4; k++) {
            int4 m = M[tid + k * 256];
            cnt += m.x + m.y + m.z + m.w;
        }
#pragma unroll
        for (int off = 16; off; off >>= 1)
            cnt += __shfl_down_sync(0xffffffffu, cnt, off);
        if (lane == 0) s_wsum[warp] = cnt;
        __syncthreads();
        if (tid == 0) {
            cnt = 0;
#pragma unroll
            for (int w = 0; w < 8; w++) cnt += s_wsum[w];
            g_ccnt[cu] = cnt;
        }
    }
    gsync(ls);

    // ================= Phase A2: finalize stats + scan chunk counts =================
    if (bx < 64 && tid == 0) {
        float s = 0.f, s2 = 0.f;
#pragma unroll
        for (int q = 0; q < 4; q++) {
            s  += g_pstat[(bx*4 + q)*2];
            s2 += g_pstat[(bx*4 + q)*2 + 1];
        }
        float mu = s * (1.f / KI);
        float var = s2 * (1.f / KI) - mu * mu;
        float sd = sqrtf(fmaxf(var, 0.f));
        g_mu[bx]  = mu;
        g_ivs[bx] = 1.f / (sd + EPS_C);
    } else if (bx >= 64 && bx < 80 && tid == 0) {
        const int b = bx - 64;
        int acc = 0;
#pragma unroll
        for (int c = 0; c < 8; c++) {
            g_cbase[b*8 + c] = acc;
            acc += g_ccnt[b*8 + c];
        }
    }
    gsync(ls);

    // ================= Phase B: pack (rf, indicator) =================
    if (bx < 128) {
        const int b = bx >> 3, chunk = bx & 7;
        const int P0 = chunk * 4096;
        const float mu0 = g_mu[b*4+0], iv0 = g_ivs[b*4+0];
        const float mu1 = g_mu[b*4+1], iv1 = g_ivs[b*4+1];
        const float mu2 = g_mu[b*4+2], iv2 = g_ivs[b*4+2];
        const float mu3 = g_mu[b*4+3], iv3 = g_ivs[b*4+3];
        const float* pC = fC + b*KI;
        const float* pA = fA + b*KI;
        const float* pD = fD + b*KI;
        const float* pB = fB + b*KI;

        int mbits[16];
        int cnt = 0;
        {
            const int4* M = (const int4*)(mask + b * KF + P0 + tid * 16);
#pragma unroll
            for (int i = 0; i < 4; i++) {
                int4 m = M[i];
                mbits[4*i] = m.x; mbits[4*i+1] = m.y; mbits[4*i+2] = m.z; mbits[4*i+3] = m.w;
                cnt += m.x + m.y + m.z + m.w;
            }
        }
        int inc = cnt;
#pragma unroll
        for (int off = 1; off < 32; off <<= 1) {
            int v = __shfl_up_sync(0xffffffffu, inc, off);
            if (lane >= off) inc += v;
        }
        if (lane == 31) s_wsum[warp] = inc;
        __syncthreads();
        int wbase = 0;
#pragma unroll
        for (int w = 0; w < 8; w++) {
            int v = s_wsum[w];
            if (w < warp) wbase += v;
        }
        int r = g_cbase[b*8 + chunk] + wbase + inc - cnt;   // rank of first hit

        float4 riv[8];
#pragma unroll
        for (int i = 0; i < 16; i++) {
            float rv, ivv;
            if (mbits[i]) {
                float zc = (pC[r] - mu0) * iv0;
                float za = (pA[r] - mu1) * iv1;
                float zd = (pD[r] - mu2) * iv2;
                float zb = (pB[r] - mu3) * iv3;
                float Ct = fmaxf(zc, 0.f);
                float At = 1.f / (1.f + fast_ex2(-za * L2E));
                float Dt = 1.f / (1.f + fast_ex2(-zd * L2E));
                float Bt = 1.f / (1.f + fast_ex2(-zb * L2E));
                float denom = fmaxf(1.f + 0.5f * (Dt + Bt), EPS_C);
                rv = Ct * At / denom;
                ivv = 1.f;
                r++;
            } else { rv = 0.f; ivv = 0.f; }
            if (i & 1) { riv[i>>1].z = rv; riv[i>>1].w = ivv; }
            else       { riv[i>>1].x = rv; riv[i>>1].y = ivv; }
        }
        float4* RIp = (float4*)(g_RI + (size_t)(b * KF + P0 + tid * 16) * 2);
#pragma unroll
        for (int i = 0; i < 8; i++) RIp[i] = riv[i];
    }
    gsync(ls);

    // ================= Phase C: score (warp per head, units strided) =================
    // unit u: b = u>>8, hg = (u>>6)&3, seg = u&63. Warp w -> row b*32+hg*8+w.
    for (int u = bx; u < 4096; u += GRID) {
        const int b   = u >> 8;
        const int hg  = (u >> 6) & 3;
        const int seg = u & 63;
        const int row = b * HH + hg * 8 + warp;
        const float* A = attn + (size_t)row * KF;
        const float4* RIf4 = (const float4*)(g_RI + (size_t)b * KF * 2);

        float zi = 0.f, p = 0.f, sm = 0.f;
#pragma unroll
        for (int half = 0; half < 2; half++) {
            const int i8 = seg * 64 + half * 32 + lane;
            F8 x = ldg256_el(A + (size_t)i8 * 8);
            const float4* ri = RIf4 + (size_t)i8 * 4;
#pragma unroll
            for (int c = 0; c < 4; c++) {
                float4 w4 = __ldg(ri + c);
                float e0 = fast_ex2(x.v[2*c]   * L2E);
                float e1 = fast_ex2(x.v[2*c+1] * L2E);
                zi = fmaf(e0, w4.y, fmaf(e1, w4.w, zi));
                p  = fmaf(e0, w4.x, fmaf(e1, w4.z, p));
                sm = fmaf(e0, fminf(w4.x, 1.f), fmaf(e1, fminf(w4.z, 1.f), sm));
            }
        }
#pragma unroll
        for (int off = 16; off; off >>= 1) {
            zi += __shfl_down_sync(0xffffffffu, zi, off);
            p  += __shfl_down_sync(0xffffffffu, p,  off);
            sm += __shfl_down_sync(0xffffffffu, sm, off);
        }
        if (lane == 0)
            g_part[row * SEGC + seg] = make_float4(zi, p, sm, 0.f);
    }
    gsync(ls);

    // ================= Phase D: finalize + top-7 select =================
    if (bx < 2) {
        const int b = bx * 8 + warp;       // warp per batch, lane per head
        const int row = b * HH + lane;
        float zi = 0.f, p = 0.f, sm = 0.f;
#pragma unroll
        for (int k = 0; k < SEGC; k++) {
            float4 v = g_part[row * SEGC + k];
            zi += v.x; p += v.y; sm += v.z;
        }
        const float sp = p / zi;
        const float sn = (zi - sm) / zi;

        bool sel = false;
#pragma unroll
        for (int t = 0; t < 7; t++) {
            float cv = sel ? -FLT_MAX : sp;
            int ci = lane;
#pragma unroll
            for (int off = 16; off; off >>= 1) {
                float ov = __shfl_down_sync(0xffffffffu, cv, off);
                int   oi = __shfl_down_sync(0xffffffffu, ci, off);
                if (ov > cv || (ov == cv && oi < ci)) { cv = ov; ci = oi; }
            }
            int win = __shfl_sync(0xffffffffu, ci, 0);
            if (lane == win) sel = true;
        }
        const bool mpos = sel && (sp > 0.f);

        const float ns = mpos ? -FLT_MAX : sn;
        sel = false;
#pragma unroll
        for (int t = 0; t < 7; t++) {
            float cv = sel ? -FLT_MAX : ns;
            int ci = lane;
#pragma unroll
            for (int off = 16; off; off >>= 1) {
                float ov = __shfl_down_sync(0xffffffffu, cv, off);
                int   oi = __shfl_down_sync(0xffffffffu, ci, off);
                if (ov > cv || (ov == cv && oi < ci)) { cv = ov; ci = oi; }
            }
            int win = __shfl_sync(0xffffffffu, ci, 0);
            if (lane == win) sel = true;
        }
        const bool mneg = sel && (ns > 0.f);

        g_ca[row] = mpos ? GAMMA_C : 0.f;
        g_cb[row] = mneg ? GAMMA_C : 0.f;
    }
    gsync(ls);

    // ================= Phase E: apply (attn L2-warm) =================
    const float4* Ap = (const float4*)attn;
    float4* Op = (float4*)out;
    const int NF4 = NROW * (KF / 4);          // 4,194,304
    for (int i = bx * 256 + tid; i < NF4; i += GRID * 256) {
        const int bh = i >> 13;
        float4 x = __ldcs(&Ap[i]);
        const float a = __ldg(&g_ca[bh]);
        const float c = __ldg(&g_cb[bh]);
        if (a == 0.f && c == 0.f) {
            __stcs(&Op[i], x);
        } else {
            const int b = bh >> 5;
            const int posf4 = i & 8191;
            const float4* RIf4 = (const float4*)(g_RI + (size_t)b * KF * 2);
            float4 r0 = RIf4[2*posf4];
            float4 r1 = RIf4[2*posf4 + 1];
            float4 o;
            float R, I, w;
            R = r0.x; I = r0.y; w = fmaxf(1.f - R, 0.f) * I;
            o.x = fmaf(a, R, fmaf(-c, w, x.x));
            R = r0.z; I = r0.w; w = fmaxf(1.f - R, 0.f) * I;
            o.y = fmaf(a, R, fmaf(-c, w, x.y));
            R = r1.x; I = r1.y; w = fmaxf(1.f - R, 0.f) * I;
            o.z = fmaf(a, R, fmaf(-c, w, x.z));
            R = r1.z; I = r1.w; w = fmaxf(1.f - R, 0.f) * I;
            o.w = fmaf(a, R, fmaf(-c, w, x.w));
            __stcs(&Op[i], o);
        }
    }
}

// ============================================================
extern "C" void kernel_launch(void* const* d_in, const int* in_sizes, int n_in,
                              void* d_out, int out_size)
{
    const float* attn = (const float*)d_in[0];
    const int*   mask = (const int*)  d_in[1];
    const float* fC   = (const float*)d_in[2];
    const float* fA   = (const float*)d_in[3];
    const float* fD   = (const float*)d_in[4];
    const float* fB   = (const float*)d_in[5];
    float* out = (float*)d_out;

    fused_kernel<<<GRID, 256>>>(attn, mask, fC, fA, fD, fB, out);
}

// round 16
// speedup vs baseline: 1.2153x; 1.1509x over previous
#include <cuda_runtime.h>
#include <math.h>
#include <float.h>

#define KF 32768
#define KI 16384
#define BB 16
#define HH 32
#define NROW (BB*HH)           // 512
#define SEGC 64                // score segments per row (64 f8 each)
#define GRID 592               // 148 SM * 4 blocks, all co-resident
#define GAMMA_C 0.3f
#define EPS_C 1e-6f
#define L2E 1.4426950408889634f

// ---- scratch (static device arrays; no allocations) ----
__device__ float  g_RI[BB * KF * 2];      // interleaved (rf, indicator)
__device__ float  g_pstat[256 * 2];       // partial (sum,sumsq) per (b,f,quarter)
__device__ int    g_ccnt[BB * 16];        // mask ones per 2048-chunk
__device__ float4 g_part[NROW * SEGC];    // per (row,seg): zi,p,sm,0
__device__ float  g_ca[NROW], g_cb[NROW];
__device__ unsigned g_cnt;                // barrier arrivals
__device__ volatile unsigned g_sense;     // barrier sense (monotonic)

__device__ __forceinline__ float fast_ex2(float x) {
    float y;
    asm("ex2.approx.ftz.f32 %0, %1;" : "=f"(y) : "f"(x));
    return y;
}

struct F8 { float v[8]; };
__device__ __forceinline__ F8 ldg256_el(const float* p) {
    unsigned r0,r1,r2,r3,r4,r5,r6,r7;
    asm volatile("ld.global.L2::evict_last.v8.b32 {%0,%1,%2,%3,%4,%5,%6,%7}, [%8];"
                 : "=r"(r0),"=r"(r1),"=r"(r2),"=r"(r3),
                   "=r"(r4),"=r"(r5),"=r"(r6),"=r"(r7) : "l"(p));
    F8 o;
    o.v[0]=__uint_as_float(r0); o.v[1]=__uint_as_float(r1);
    o.v[2]=__uint_as_float(r2); o.v[3]=__uint_as_float(r3);
    o.v[4]=__uint_as_float(r4); o.v[5]=__uint_as_float(r5);
    o.v[6]=__uint_as_float(r6); o.v[7]=__uint_as_float(r7);
    return o;
}

// grid barrier: all GRID blocks co-resident (enforced by __launch_bounds__)
__device__ __forceinline__ void gsync(unsigned& ls) {
    __threadfence();
    __syncthreads();
    if (threadIdx.x == 0) {
        ls++;
        if (atomicAdd(&g_cnt, 1u) == GRID - 1) {
            atomicExch(&g_cnt, 0u);
            __threadfence();
            g_sense = ls;       // release
        } else {
            while (g_sense != ls) __nanosleep(64);
            __threadfence();
        }
    }
    __syncthreads();
}

__global__ void __launch_bounds__(256, 4) fused_kernel(
    const float* __restrict__ attn, const int* __restrict__ mask,
    const float* __restrict__ fC, const float* __restrict__ fA,
    const float* __restrict__ fD, const float* __restrict__ fB,
    float* __restrict__ out)
{
    const int bx = blockIdx.x;
    const int tid = threadIdx.x;
    const int lane = tid & 31, warp = tid >> 5;
    unsigned ls = g_sense;   // stable at kernel start (before any release)

    __shared__ float s_r1[8], s_r2[8];
    __shared__ int   s_wsum[8];

    const float* fptr[4] = {fC, fA, fD, fB};

    // ========= Phase A: stats partials (blocks 0-255) + mask chunk counts (256-511) =========
    if (bx < 256) {
        const int bf = bx >> 2, quarter = bx & 3;
        const int b = bf >> 2, f = bf & 3;
        const float4* P = (const float4*)(fptr[f] + b * KI + quarter * 4096);
        float s = 0.f, s2 = 0.f;
#pragma unroll
        for (int k = 0; k < 4; k++) {
            float4 v = P[tid + k * 256];
            s  += (v.x + v.y) + (v.z + v.w);
            s2 += (v.x*v.x + v.y*v.y) + (v.z*v.z + v.w*v.w);
        }
#pragma unroll
        for (int off = 16; off; off >>= 1) {
            s  += __shfl_down_sync(0xffffffffu, s,  off);
            s2 += __shfl_down_sync(0xffffffffu, s2, off);
        }
        if (lane == 0) { s_r1[warp] = s; s_r2[warp] = s2; }
        __syncthreads();
        if (tid == 0) {
            s = 0.f; s2 = 0.f;
#pragma unroll
            for (int w = 0; w < 8; w++) { s += s_r1[w]; s2 += s_r2[w]; }
            g_pstat[bx*2]   = s;
            g_pstat[bx*2+1] = s2;
        }
    } else if (bx < 512) {
        const int cu = bx - 256;         // b*16 + chunk
        const int b = cu >> 4, chunk = cu & 15;
        const int4* M = (const int4*)(mask + b * KF + chunk * 2048);
        int cnt = 0;
#pragma unroll
        for (int k = 0; k < 2; k++) {
            int4 m = M[tid + k * 256];
            cnt += m.x + m.y + m.z + m.w;
        }
#pragma unroll
        for (int off = 16; off; off >>= 1)
            cnt += __shfl_down_sync(0xffffffffu, cnt, off);
        if (lane == 0) s_wsum[warp] = cnt;
        __syncthreads();
        if (tid == 0) {
            cnt = 0;
#pragma unroll
            for (int w = 0; w < 8; w++) cnt += s_wsum[w];
            g_ccnt[cu] = cnt;
        }
    }
    gsync(ls);

    // ========= Phase B: pack (rf, indicator). 256 blocks, chunk=2048 positions =========
    if (bx < 256) {
        const int b = bx >> 4, chunk = bx & 15;
        const int P0 = chunk * 2048;

        // redundant per-block stats finalize (32 tiny L2 reads)
        float mu[4], ivs[4];
#pragma unroll
        for (int f = 0; f < 4; f++) {
            float s = 0.f, s2 = 0.f;
#pragma unroll
            for (int q = 0; q < 4; q++) {
                s  += g_pstat[((b*4+f)*4 + q)*2];
                s2 += g_pstat[((b*4+f)*4 + q)*2 + 1];
            }
            float m = s * (1.f / KI);
            float var = s2 * (1.f / KI) - m * m;
            mu[f]  = m;
            ivs[f] = 1.f / (sqrtf(fmaxf(var, 0.f)) + EPS_C);
        }
        // redundant chunk-rank base
        int cbase = 0;
        for (int c = 0; c < chunk; c++) cbase += g_ccnt[b*16 + c];

        const float* pC = fC + b*KI;
        const float* pA = fA + b*KI;
        const float* pD = fD + b*KI;
        const float* pB = fB + b*KI;

        int mbits[8];
        int cnt = 0;
        {
            const int4* M = (const int4*)(mask + b * KF + P0 + tid * 8);
            int4 m0 = M[0], m1 = M[1];
            mbits[0]=m0.x; mbits[1]=m0.y; mbits[2]=m0.z; mbits[3]=m0.w;
            mbits[4]=m1.x; mbits[5]=m1.y; mbits[6]=m1.z; mbits[7]=m1.w;
            cnt = m0.x+m0.y+m0.z+m0.w + m1.x+m1.y+m1.z+m1.w;
        }
        int inc = cnt;
#pragma unroll
        for (int off = 1; off < 32; off <<= 1) {
            int v = __shfl_up_sync(0xffffffffu, inc, off);
            if (lane >= off) inc += v;
        }
        if (lane == 31) s_wsum[warp] = inc;
        __syncthreads();
        int wbase = 0;
#pragma unroll
        for (int w = 0; w < 8; w++) {
            int v = s_wsum[w];
            if (w < warp) wbase += v;
        }
        int r = cbase + wbase + inc - cnt;   // rank of this thread's first image pos

        float4 riv[4];
#pragma unroll
        for (int i = 0; i < 8; i++) {
            float rv, ivv;
            if (mbits[i]) {
                float zc = (pC[r] - mu[0]) * ivs[0];
                float za = (pA[r] - mu[1]) * ivs[1];
                float zd = (pD[r] - mu[2]) * ivs[2];
                float zb = (pB[r] - mu[3]) * ivs[3];
                float Ct = fmaxf(zc, 0.f);
                float At = 1.f / (1.f + fast_ex2(-za * L2E));
                float Dt = 1.f / (1.f + fast_ex2(-zd * L2E));
                float Bt = 1.f / (1.f + fast_ex2(-zb * L2E));
                float denom = fmaxf(1.f + 0.5f * (Dt + Bt), EPS_C);
                rv = Ct * At / denom;
                ivv = 1.f;
                r++;
            } else { rv = 0.f; ivv = 0.f; }
            if (i & 1) { riv[i>>1].z = rv; riv[i>>1].w = ivv; }
            else       { riv[i>>1].x = rv; riv[i>>1].y = ivv; }
        }
        float4* RIp = (float4*)(g_RI + (size_t)(b * KF + P0 + tid * 8) * 2);
#pragma unroll
        for (int i = 0; i < 4; i++) RIp[i] = riv[i];
    }
    gsync(ls);

    // ========= Phase C: score (warp per head; both attn loads front-batched) =========
    for (int u = bx; u < 4096; u += GRID) {
        const int b   = u >> 8;
        const int hg  = (u >> 6) & 3;
        const int seg = u & 63;
        const int row = b * HH + hg * 8 + warp;
        const int i8 = seg * 64 + lane;
        const float* A = attn + (size_t)row * KF + (size_t)i8 * 8;

        F8 x0 = ldg256_el(A);            // front-batched: both loads in flight
        F8 x1 = ldg256_el(A + 256);

        const float4* ri0 = (const float4*)(g_RI + (size_t)b * KF * 2) + (size_t)i8 * 4;
        const float4* ri1 = ri0 + 128;   // +32 f8 positions

        float zi = 0.f, p = 0.f, sm = 0.f;
#pragma unroll
        for (int c = 0; c < 4; c++) {
            float4 w4 = __ldg(ri0 + c);
            float e0 = fast_ex2(x0.v[2*c]   * L2E);
            float e1 = fast_ex2(x0.v[2*c+1] * L2E);
            zi = fmaf(e0, w4.y, fmaf(e1, w4.w, zi));
            p  = fmaf(e0, w4.x, fmaf(e1, w4.z, p));
            sm = fmaf(e0, fminf(w4.x, 1.f), fmaf(e1, fminf(w4.z, 1.f), sm));
        }
#pragma unroll
        for (int c = 0; c < 4; c++) {
            float4 w4 = __ldg(ri1 + c);
            float e0 = fast_ex2(x1.v[2*c]   * L2E);
            float e1 = fast_ex2(x1.v[2*c+1] * L2E);
            zi = fmaf(e0, w4.y, fmaf(e1, w4.w, zi));
            p  = fmaf(e0, w4.x, fmaf(e1, w4.z, p));
            sm = fmaf(e0, fminf(w4.x, 1.f), fmaf(e1, fminf(w4.z, 1.f), sm));
        }
#pragma unroll
        for (int off = 16; off; off >>= 1) {
            zi += __shfl_down_sync(0xffffffffu, zi, off);
            p  += __shfl_down_sync(0xffffffffu, p,  off);
            sm += __shfl_down_sync(0xffffffffu, sm, off);
        }
        if (lane == 0)
            g_part[row * SEGC + seg] = make_float4(zi, p, sm, 0.f);
    }
    gsync(ls);

    // ========= Phase D: finalize + top-7 select (2 blocks, warp per batch) =========
    if (bx < 2) {
        const int b = bx * 8 + warp;
        const int row = b * HH + lane;
        float zi = 0.f, p = 0.f, sm = 0.f;
#pragma unroll
        for (int k = 0; k < SEGC; k++) {
            float4 v = g_part[row * SEGC + k];
            zi += v.x; p += v.y; sm += v.z;
        }
        const float sp = p / zi;
        const float sn = (zi - sm) / zi;

        bool sel = false;
#pragma unroll
        for (int t = 0; t < 7; t++) {
            float cv = sel ? -FLT_MAX : sp;
            int ci = lane;
#pragma unroll
            for (int off = 16; off; off >>= 1) {
                float ov = __shfl_down_sync(0xffffffffu, cv, off);
                int   oi = __shfl_down_sync(0xffffffffu, ci, off);
                if (ov > cv || (ov == cv && oi < ci)) { cv = ov; ci = oi; }
            }
            int win = __shfl_sync(0xffffffffu, ci, 0);
            if (lane == win) sel = true;
        }
        const bool mpos = sel && (sp > 0.f);

        const float ns = mpos ? -FLT_MAX : sn;
        sel = false;
#pragma unroll
        for (int t = 0; t < 7; t++) {
            float cv = sel ? -FLT_MAX : ns;
            int ci = lane;
#pragma unroll
            for (int off = 16; off; off >>= 1) {
                float ov = __shfl_down_sync(0xffffffffu, cv, off);
                int   oi = __shfl_down_sync(0xffffffffu, ci, off);
                if (ov > cv || (ov == cv && oi < ci)) { cv = ov; ci = oi; }
            }
            int win = __shfl_sync(0xffffffffu, ci, 0);
            if (lane == win) sel = true;
        }
        const bool mneg = sel && (ns > 0.f);

        g_ca[row] = mpos ? GAMMA_C : 0.f;
        g_cb[row] = mneg ? GAMMA_C : 0.f;
    }
    gsync(ls);

    // ========= Phase E: apply (attn L2-warm), paired-stride for MLP =========
    const float4* Ap = (const float4*)attn;
    float4* Op = (float4*)out;
    const int NF4 = NROW * (KF / 4);          // 4,194,304
    const int stride = GRID * 256;

    for (int i = bx * 256 + tid; i < NF4; i += 2 * stride) {
        const int j = i + stride;
        const bool hasB = (j < NF4);

        float4 xA = __ldcs(&Ap[i]);
        float4 xB;
        if (hasB) xB = __ldcs(&Ap[j]);

        {
            const int bh = i >> 13;
            const float a = __ldg(&g_ca[bh]);
            const float c = __ldg(&g_cb[bh]);
            if (a == 0.f && c == 0.f) {
                __stcs(&Op[i], xA);
            } else {
                const int b = bh >> 5;
                const int posf4 = i & 8191;
                const float4* RIf4 = (const float4*)(g_RI + (size_t)b * KF * 2);
                float4 r0 = RIf4[2*posf4];
                float4 r1 = RIf4[2*posf4 + 1];
                float4 o;
                float R, I, w;
                R = r0.x; I = r0.y; w = fmaxf(1.f - R, 0.f) * I;
                o.x = fmaf(a, R, fmaf(-c, w, xA.x));
                R = r0.z; I = r0.w; w = fmaxf(1.f - R, 0.f) * I;
                o.y = fmaf(a, R, fmaf(-c, w, xA.y));
                R = r1.x; I = r1.y; w = fmaxf(1.f - R, 0.f) * I;
                o.z = fmaf(a, R, fmaf(-c, w, xA.z));
                R = r1.z; I = r1.w; w = fmaxf(1.f - R, 0.f) * I;
                o.w = fmaf(a, R, fmaf(-c, w, xA.w));
                __stcs(&Op[i], o);
            }
        }
        if (hasB) {
            const int bh = j >> 13;
            const float a = __ldg(&g_ca[bh]);
            const float c = __ldg(&g_cb[bh]);
            if (a == 0.f && c == 0.f) {
                __stcs(&Op[j], xB);
            } else {
                const int b = bh >> 5;
                const int posf4 = j & 8191;
                const float4* RIf4 = (const float4*)(g_RI + (size_t)b * KF * 2);
                float4 r0 = RIf4[2*posf4];
                float4 r1 = RIf4[2*posf4 + 1];
                float4 o;
                float R, I, w;
                R = r0.x; I = r0.y; w = fmaxf(1.f - R, 0.f) * I;
                o.x = fmaf(a, R, fmaf(-c, w, xB.x));
                R = r0.z; I = r0.w; w = fmaxf(1.f - R, 0.f) * I;
                o.y = fmaf(a, R, fmaf(-c, w, xB.y));
                R = r1.x; I = r1.y; w = fmaxf(1.f - R, 0.f) * I;
                o.z = fmaf(a, R, fmaf(-c, w, xB.z));
                R = r1.z; I = r1.w; w = fmaxf(1.f - R, 0.f) * I;
                o.w = fmaf(a, R, fmaf(-c, w, xB.w));
                __stcs(&Op[j], o);
            }
        }
    }
}

// ============================================================
extern "C" void kernel_launch(void* const* d_in, const int* in_sizes, int n_in,
                              void* d_out, int out_size)
{
    const float* attn = (const float*)d_in[0];
    const int*   mask = (const int*)  d_in[1];
    const float* fC   = (const float*)d_in[2];
    const float* fA   = (const float*)d_in[3];
    const float* fD   = (const float*)d_in[4];
    const float* fB   = (const float*)d_in[5];
    float* out = (float*)d_out;

    fused_kernel<<<GRID, 256>>>(attn, mask, fC, fA, fD, fB, out);
}